// round 7
// baseline (speedup 1.0000x reference)
#include <cuda_runtime.h>
#include <math.h>

#define BATCH 16
#define DIM   512
#define S     128
#define PLANE (S*S)
#define PLANE4 (PLANE/4)
#define CSPLIT 4
#define CPER  (DIM/CSPLIT)     // 128 channels per split

// Accumulator for fused strip-conv partials:
// g_TR[b][0..4][w]   = T[kw][w']  (ww branch, pre-halo)
// g_TR[b][5..9][h]   = R[kh][h']  (hw branch, pre-halo)
// Invariant: zero on entry to kernel_launch (zero-init at load, re-zeroed by
// the in-kernel tail after each use). g_cnt likewise.
__device__ float g_TR[BATCH * 10 * S];
__device__ int   g_cnt[BATCH];

// ---------------------------------------------------------------------------
// Single fused kernel: 1x1 conv 512->2 + strip-conv partials; the last block
// to finish each batch runs the tail (halo + GEMV + sigmoid + outer product).
// Block = 128 threads = 32 pixel4 (one image row) x 4 channel-splits.
// Grid = 2048 (16 b x 128 rows). x2 never touches DRAM.
// ---------------------------------------------------------------------------
__global__ void __launch_bounds__(128, 16)
k_fused(const float* __restrict__ x,
        const float* __restrict__ wconv,
        const float* __restrict__ w_ww,
        const float* __restrict__ w_hw,
        const float* __restrict__ ww_lw,
        const float* __restrict__ ww_lb,
        const float* __restrict__ hw_lw,
        const float* __restrict__ hw_lb,
        float* __restrict__ out) {
    __shared__ float2 s_wc[DIM];            // 4 KB
    __shared__ float4 red0[CSPLIT][32];     // 2 KB
    __shared__ float4 red1[CSPLIT][32];     // 2 KB
    __shared__ float  s_T[5][S];            // 2.5 KB
    __shared__ int    s_last;
    // tail scratch
    __shared__ float  t_in[2 * S];          // 1 KB
    __shared__ __align__(16) float t_ww[S];
    __shared__ float  t_hw[S];

    int tid = threadIdx.x;
    for (int c = tid; c < DIM; c += 128)
        s_wc[c] = make_float2(wconv[c], wconv[DIM + c]);
    for (int k = tid; k < 5 * S; k += 128)
        (&s_T[0][0])[k] = 0.f;
    __syncthreads();

    int s = tid >> 5;                  // channel split 0..3
    int p = tid & 31;                  // pixel4 within row
    int b  = blockIdx.x >> 7;          // batch
    int rb = blockIdx.x & 127;         // row index

    const float4* xb = reinterpret_cast<const float4*>(x)
                     + (size_t)b * DIM * PLANE4
                     + (size_t)s * CPER * PLANE4
                     + (size_t)rb * 32 + p;

    float4 a0 = make_float4(0.f, 0.f, 0.f, 0.f);
    float4 a1 = make_float4(0.f, 0.f, 0.f, 0.f);

    for (int c0 = 0; c0 < CPER; c0 += 8) {
        float4 v[8];
#pragma unroll
        for (int j = 0; j < 8; j++)
            v[j] = xb[(size_t)(c0 + j) * PLANE4];
#pragma unroll
        for (int j = 0; j < 8; j++) {
            float2 wc = s_wc[s * CPER + c0 + j];
            a0.x = fmaf(v[j].x, wc.x, a0.x); a0.y = fmaf(v[j].y, wc.x, a0.y);
            a0.z = fmaf(v[j].z, wc.x, a0.z); a0.w = fmaf(v[j].w, wc.x, a0.w);
            a1.x = fmaf(v[j].x, wc.y, a1.x); a1.y = fmaf(v[j].y, wc.y, a1.y);
            a1.z = fmaf(v[j].z, wc.y, a1.z); a1.w = fmaf(v[j].w, wc.y, a1.w);
        }
    }

    red0[s][p] = a0;
    red1[s][p] = a1;
    __syncthreads();

    // Threads 0..63: combine splits -> final x2 row values, emit partials.
    if (tid < 64) {
        int ch = tid >> 5;
        int pp = tid & 31;
        float4 r;
        {
            float4 q0, q1, q2, q3;
            if (ch == 0) { q0 = red0[0][pp]; q1 = red0[1][pp]; q2 = red0[2][pp]; q3 = red0[3][pp]; }
            else         { q0 = red1[0][pp]; q1 = red1[1][pp]; q2 = red1[2][pp]; q3 = red1[3][pp]; }
            r = make_float4(q0.x + q1.x + q2.x + q3.x, q0.y + q1.y + q2.y + q3.y,
                            q0.z + q1.z + q2.z + q3.z, q0.w + q1.w + q2.w + q3.w);
        }
        int w0 = pp * 4;

        // T[kw][w'] += x2[ch, rb, w'] * w_ww[ch, rb, kw]   (w_ww: [2,128,5])
#pragma unroll
        for (int kw = 0; kw < 5; kw++) {
            float wt = __ldg(&w_ww[(ch * S + rb) * 5 + kw]);
            atomicAdd(&s_T[kw][w0 + 0], r.x * wt);
            atomicAdd(&s_T[kw][w0 + 1], r.y * wt);
            atomicAdd(&s_T[kw][w0 + 2], r.z * wt);
            atomicAdd(&s_T[kw][w0 + 3], r.w * wt);
        }

        // R[kh][rb] += sum_w x2[ch, rb, w] * w_hw[ch, kh, w]   (w_hw: [2,5,128])
#pragma unroll
        for (int kh = 0; kh < 5; kh++) {
            const float* whp = w_hw + (ch * 5 + kh) * S + w0;
            float pr = r.x * __ldg(whp) + r.y * __ldg(whp + 1)
                     + r.z * __ldg(whp + 2) + r.w * __ldg(whp + 3);
#pragma unroll
            for (int off = 16; off > 0; off >>= 1)
                pr += __shfl_down_sync(0xFFFFFFFFu, pr, off);
            if (pp == 0)
                atomicAdd(&g_TR[b * (10 * S) + (5 + kh) * S + rb], pr);
        }
    }
    __syncthreads();

    // Flush block-local T to global accumulator
    for (int k = tid; k < 5 * S; k += 128)
        atomicAdd(&g_TR[b * (10 * S) + k], (&s_T[0][0])[k]);

    // ---- completion detection ----
    __syncthreads();
    if (tid == 0) {
        __threadfence();
        int old = atomicAdd(&g_cnt[b], 1);
        s_last = (old == 127) ? 1 : 0;
    }
    __syncthreads();
    if (!s_last) return;

    // =========================== TAIL (1 block / batch) =====================
    __threadfence();                        // acquire all g_TR updates
    float* TR = g_TR + b * (10 * S);

    // Halo combine: thread t produces ww input [t] and hw input [t]
    {
        float accw = 0.f, acch = 0.f;
#pragma unroll
        for (int k5 = 0; k5 < 5; k5++) {
            int ip = tid + k5 - 2;
            if (ip >= 0 && ip < S) {
                accw += TR[k5 * S + ip];
                acch += TR[(5 + k5) * S + ip];
            }
        }
        t_in[tid]     = accw;
        t_in[S + tid] = acch;
    }
    __syncthreads();

    // Dual GEMV: 4 warps, 256 warp-outputs total; lanes stride over k.
    {
        int warp = tid >> 5, lane = tid & 31;
#pragma unroll 4
        for (int jj = warp; jj < 2 * S; jj += 4) {
            int branch = jj >> 7;
            int j      = jj & 127;
            const float* row = (branch ? hw_lw : ww_lw) + j * S;
            const float* vin = t_in + branch * S;
            float acc = 0.f;
#pragma unroll
            for (int kk = 0; kk < 4; kk++) {
                int k = lane + kk * 32;
                acc = fmaf(vin[k], __ldg(&row[k]), acc);
            }
#pragma unroll
            for (int off = 16; off > 0; off >>= 1)
                acc += __shfl_down_sync(0xFFFFFFFFu, acc, off);
            if (lane == 0) {
                acc += __ldg(branch ? &hw_lb[j] : &ww_lb[j]);
                float sg = 1.f / (1.f + expf(-acc));
                if (branch == 0) t_ww[j] = sg;
                else             t_hw[j] = sg;
            }
        }
    }

    // Reset state for next kernel_launch call
    for (int k = tid; k < 10 * S; k += 128) TR[k] = 0.f;
    if (tid == 0) g_cnt[b] = 0;
    __syncthreads();

    // Outer product: out[b,h,w] = hw[h] * ww[w]
    float4* o4 = reinterpret_cast<float4*>(out + (size_t)b * PLANE);
    const float4* wv4 = reinterpret_cast<const float4*>(t_ww);
#pragma unroll
    for (int it = 0; it < 32; it++) {
        int q  = tid + it * 128;
        int h  = q >> 5;
        int w4 = q & 31;
        float hv = t_hw[h];
        float4 wv = wv4[w4];
        o4[q] = make_float4(hv * wv.x, hv * wv.y, hv * wv.z, hv * wv.w);
    }
}

// ---------------------------------------------------------------------------
extern "C" void kernel_launch(void* const* d_in, const int* in_sizes, int n_in,
                              void* d_out, int out_size) {
    const float* x      = (const float*)d_in[0];
    const float* w_conv = (const float*)d_in[1];
    const float* w_ww   = (const float*)d_in[2];
    const float* w_hw   = (const float*)d_in[3];
    const float* ww_lw  = (const float*)d_in[4];
    const float* ww_lb  = (const float*)d_in[5];
    const float* hw_lw  = (const float*)d_in[6];
    const float* hw_lb  = (const float*)d_in[7];
    float* out = (float*)d_out;

    k_fused<<<2048, 128>>>(x, w_conv, w_ww, w_hw,
                           ww_lw, ww_lb, hw_lw, hw_lb, out);
}

// round 9
// speedup vs baseline: 1.2999x; 1.2999x over previous
#include <cuda_runtime.h>
#include <math.h>

#define BATCH 16
#define DIM   512
#define S     128
#define PLANE (S*S)
#define PLANE4 (PLANE/4)
#define CSPLIT 4
#define CPER  (DIM/CSPLIT)     // 128 channels per split

// Accumulator for fused strip-conv partials:
// g_TR[b][0..4][w]   = T[kw][w']  (ww branch, pre-halo)
// g_TR[b][5..9][h]   = R[kh][h']  (hw branch, pre-halo)
// Invariant: zero on entry to kernel_launch (zero-initialized at module load,
// re-zeroed by k_vec after each use) -> no memset launch needed.
__device__ float g_TR[BATCH * 10 * S];
__device__ float g_vec[BATCH * 2 * S];     // sigmoid outputs: [b][0]=ww, [b][1]=hw

// ---------------------------------------------------------------------------
// K1: 1x1 conv 512->2 fused with strip-conv partial reductions.
// (Round-5 version verbatim — measured 85.9us @ 79.6% DRAM. Do not touch.)
// Block = 128 threads = 32 pixel4 (one image row) x 4 channel-splits.
// Grid = 2048 (16 b x 128 rows). No x2 ever written to DRAM.
// ---------------------------------------------------------------------------
__global__ void __launch_bounds__(128) k_conv_fused(const float* __restrict__ x,
                                                    const float* __restrict__ wconv,
                                                    const float* __restrict__ w_ww,
                                                    const float* __restrict__ w_hw) {
    __shared__ float2 s_wc[DIM];          // 4 KB
    __shared__ float4 red0[CSPLIT][32];   // 2 KB
    __shared__ float4 red1[CSPLIT][32];   // 2 KB
    __shared__ float  s_T[5][S];          // 2.5 KB

    int tid = threadIdx.x;
    for (int c = tid; c < DIM; c += 128)
        s_wc[c] = make_float2(wconv[c], wconv[DIM + c]);
    for (int k = tid; k < 5 * S; k += 128)
        (&s_T[0][0])[k] = 0.f;
    __syncthreads();

    int s = tid >> 5;                  // channel split 0..3
    int p = tid & 31;                  // pixel4 within row
    int b  = blockIdx.x >> 7;          // batch
    int rb = blockIdx.x & 127;         // row index

    const float4* xb = reinterpret_cast<const float4*>(x)
                     + (size_t)b * DIM * PLANE4
                     + (size_t)s * CPER * PLANE4
                     + (size_t)rb * 32 + p;

    float4 a0 = make_float4(0.f, 0.f, 0.f, 0.f);
    float4 a1 = make_float4(0.f, 0.f, 0.f, 0.f);

    for (int c0 = 0; c0 < CPER; c0 += 8) {
        float4 v[8];
#pragma unroll
        for (int j = 0; j < 8; j++)
            v[j] = xb[(size_t)(c0 + j) * PLANE4];
#pragma unroll
        for (int j = 0; j < 8; j++) {
            float2 wc = s_wc[s * CPER + c0 + j];
            a0.x = fmaf(v[j].x, wc.x, a0.x); a0.y = fmaf(v[j].y, wc.x, a0.y);
            a0.z = fmaf(v[j].z, wc.x, a0.z); a0.w = fmaf(v[j].w, wc.x, a0.w);
            a1.x = fmaf(v[j].x, wc.y, a1.x); a1.y = fmaf(v[j].y, wc.y, a1.y);
            a1.z = fmaf(v[j].z, wc.y, a1.z); a1.w = fmaf(v[j].w, wc.y, a1.w);
        }
    }

    red0[s][p] = a0;
    red1[s][p] = a1;
    __syncthreads();

    // Threads 0..63: combine splits -> final x2 row values, emit partials.
    if (tid < 64) {
        int ch = tid >> 5;
        int pp = tid & 31;
        float4 r;
        {
            float4 q0, q1, q2, q3;
            if (ch == 0) { q0 = red0[0][pp]; q1 = red0[1][pp]; q2 = red0[2][pp]; q3 = red0[3][pp]; }
            else         { q0 = red1[0][pp]; q1 = red1[1][pp]; q2 = red1[2][pp]; q3 = red1[3][pp]; }
            r = make_float4(q0.x + q1.x + q2.x + q3.x, q0.y + q1.y + q2.y + q3.y,
                            q0.z + q1.z + q2.z + q3.z, q0.w + q1.w + q2.w + q3.w);
        }
        int w0 = pp * 4;

        // T[kw][w'] += x2[ch, rb, w'] * w_ww[ch, rb, kw]   (w_ww: [2,128,5])
#pragma unroll
        for (int kw = 0; kw < 5; kw++) {
            float wt = __ldg(&w_ww[(ch * S + rb) * 5 + kw]);
            atomicAdd(&s_T[kw][w0 + 0], r.x * wt);
            atomicAdd(&s_T[kw][w0 + 1], r.y * wt);
            atomicAdd(&s_T[kw][w0 + 2], r.z * wt);
            atomicAdd(&s_T[kw][w0 + 3], r.w * wt);
        }

        // R[kh][rb] += sum_w x2[ch, rb, w] * w_hw[ch, kh, w]   (w_hw: [2,5,128])
#pragma unroll
        for (int kh = 0; kh < 5; kh++) {
            const float* whp = w_hw + (ch * 5 + kh) * S + w0;
            float pr = r.x * __ldg(whp) + r.y * __ldg(whp + 1)
                     + r.z * __ldg(whp + 2) + r.w * __ldg(whp + 3);
#pragma unroll
            for (int off = 16; off > 0; off >>= 1)
                pr += __shfl_down_sync(0xFFFFFFFFu, pr, off);
            if (pp == 0)
                atomicAdd(&g_TR[b * (10 * S) + (5 + kh) * S + rb], pr);
        }
    }
    __syncthreads();

    // Flush block-local T to global accumulator
    for (int k = tid; k < 5 * S; k += 128)
        atomicAdd(&g_TR[b * (10 * S) + k], (&s_T[0][0])[k]);
}

// ---------------------------------------------------------------------------
// K2: halo-combine + linear + sigmoid. Grid = 32 (b x branch), 256 threads.
// Warp-per-output GEMV: lanes stride over k -> coalesced weight rows.
// Also re-zeroes its g_TR slice for the next call (replaces memset launch).
// ---------------------------------------------------------------------------
__global__ void __launch_bounds__(256) k_vec(const float* __restrict__ ww_lw,
                                             const float* __restrict__ ww_lb,
                                             const float* __restrict__ hw_lw,
                                             const float* __restrict__ hw_lb) {
    int b      = blockIdx.x >> 1;
    int branch = blockIdx.x & 1;       // 0 = ww, 1 = hw
    int tid    = threadIdx.x;
    int warp   = tid >> 5, lane = tid & 31;

    const float* lw = branch ? hw_lw : ww_lw;
    const float* lb = branch ? hw_lb : ww_lb;
    float* TR = g_TR + b * (10 * S) + branch * (5 * S);

    __shared__ float s_in[S];

    if (tid < S) {
        float acc = 0.f;
#pragma unroll
        for (int k5 = 0; k5 < 5; k5++) {
            int ip = tid + k5 - 2;
            if (ip >= 0 && ip < S) acc += TR[k5 * S + ip];
        }
        s_in[tid] = acc;
    }
    __syncthreads();

    // Re-zero this block's TR slice (invariant for next kernel_launch call).
    for (int k = tid; k < 5 * S; k += 256) TR[k] = 0.f;

    // 8 warps x 16 outputs each
    for (int j = warp; j < S; j += 8) {
        const float* row = lw + j * S;
        float acc = 0.f;
#pragma unroll
        for (int kk = 0; kk < 4; kk++) {
            int k = lane + kk * 32;
            acc = fmaf(s_in[k], __ldg(&row[k]), acc);   // coalesced over lanes
        }
#pragma unroll
        for (int off = 16; off > 0; off >>= 1)
            acc += __shfl_down_sync(0xFFFFFFFFu, acc, off);
        if (lane == 0) {
            acc += __ldg(&lb[j]);
            g_vec[(b * 2 + branch) * S + j] = 1.f / (1.f + expf(-acc));
        }
    }
}

// ---------------------------------------------------------------------------
// K3: outer product, full-chip. 256 blocks x 256 threads, one float4/thread.
// out[b,h,w] = hw[b,h] * ww[b,w]
// ---------------------------------------------------------------------------
__global__ void __launch_bounds__(256) k_outer(float* __restrict__ out) {
    int gid = blockIdx.x * 256 + threadIdx.x;   // 0 .. 65535
    int b   = gid >> 12;
    int rem = gid & 4095;
    int h   = rem >> 5;
    int w4  = rem & 31;

    float hv = __ldg(&g_vec[(b * 2 + 1) * S + h]);
    float4 wv = __ldg(reinterpret_cast<const float4*>(&g_vec[(b * 2 + 0) * S]) + w4);

    reinterpret_cast<float4*>(out)[gid] =
        make_float4(hv * wv.x, hv * wv.y, hv * wv.z, hv * wv.w);
}

// ---------------------------------------------------------------------------
extern "C" void kernel_launch(void* const* d_in, const int* in_sizes, int n_in,
                              void* d_out, int out_size) {
    const float* x      = (const float*)d_in[0];
    const float* w_conv = (const float*)d_in[1];
    const float* w_ww   = (const float*)d_in[2];
    const float* w_hw   = (const float*)d_in[3];
    const float* ww_lw  = (const float*)d_in[4];
    const float* ww_lb  = (const float*)d_in[5];
    const float* hw_lw  = (const float*)d_in[6];
    const float* hw_lb  = (const float*)d_in[7];
    float* out = (float*)d_out;

    k_conv_fused<<<2048, 128>>>(x, w_conv, w_ww, w_hw);
    k_vec<<<32, 256>>>(ww_lw, ww_lb, hw_lw, hw_lb);
    k_outer<<<256, 256>>>(out);
}

// round 11
// speedup vs baseline: 1.5993x; 1.2303x over previous
#include <cuda_runtime.h>
#include <math.h>

#define BATCH 16
#define DIM   512
#define S     128
#define PLANE (S*S)
#define PLANE4 (PLANE/4)
#define CSPLIT 4
#define CPER  (DIM/CSPLIT)     // 128 channels per split

// Accumulator for fused strip-conv partials:
// g_TR[b][0..4][w]   = T[kw][w']  (ww branch, pre-halo)
// g_TR[b][5..9][h]   = R[kh][h']  (hw branch, pre-halo)
// Invariant: zero on entry to kernel_launch (zero-initialized at module load,
// re-zeroed by k_outer after each use).
__device__ float g_TR[BATCH * 10 * S];
__device__ float g_vec[BATCH * 2 * S];     // sigmoid outputs: [b][0]=ww, [b][1]=hw

// ---------------------------------------------------------------------------
// K1: 1x1 conv 512->2 fused with strip-conv partial reductions.
// (Round-5 version verbatim — measured 85.9-89.9us @ 76-80% DRAM. FROZEN.)
// ---------------------------------------------------------------------------
__global__ void __launch_bounds__(128) k_conv_fused(const float* __restrict__ x,
                                                    const float* __restrict__ wconv,
                                                    const float* __restrict__ w_ww,
                                                    const float* __restrict__ w_hw) {
    __shared__ float2 s_wc[DIM];          // 4 KB
    __shared__ float4 red0[CSPLIT][32];   // 2 KB
    __shared__ float4 red1[CSPLIT][32];   // 2 KB
    __shared__ float  s_T[5][S];          // 2.5 KB

    int tid = threadIdx.x;
    for (int c = tid; c < DIM; c += 128)
        s_wc[c] = make_float2(wconv[c], wconv[DIM + c]);
    for (int k = tid; k < 5 * S; k += 128)
        (&s_T[0][0])[k] = 0.f;
    __syncthreads();

    int s = tid >> 5;                  // channel split 0..3
    int p = tid & 31;                  // pixel4 within row
    int b  = blockIdx.x >> 7;          // batch
    int rb = blockIdx.x & 127;         // row index

    const float4* xb = reinterpret_cast<const float4*>(x)
                     + (size_t)b * DIM * PLANE4
                     + (size_t)s * CPER * PLANE4
                     + (size_t)rb * 32 + p;

    float4 a0 = make_float4(0.f, 0.f, 0.f, 0.f);
    float4 a1 = make_float4(0.f, 0.f, 0.f, 0.f);

    for (int c0 = 0; c0 < CPER; c0 += 8) {
        float4 v[8];
#pragma unroll
        for (int j = 0; j < 8; j++)
            v[j] = xb[(size_t)(c0 + j) * PLANE4];
#pragma unroll
        for (int j = 0; j < 8; j++) {
            float2 wc = s_wc[s * CPER + c0 + j];
            a0.x = fmaf(v[j].x, wc.x, a0.x); a0.y = fmaf(v[j].y, wc.x, a0.y);
            a0.z = fmaf(v[j].z, wc.x, a0.z); a0.w = fmaf(v[j].w, wc.x, a0.w);
            a1.x = fmaf(v[j].x, wc.y, a1.x); a1.y = fmaf(v[j].y, wc.y, a1.y);
            a1.z = fmaf(v[j].z, wc.y, a1.z); a1.w = fmaf(v[j].w, wc.y, a1.w);
        }
    }

    red0[s][p] = a0;
    red1[s][p] = a1;
    __syncthreads();

    if (tid < 64) {
        int ch = tid >> 5;
        int pp = tid & 31;
        float4 r;
        {
            float4 q0, q1, q2, q3;
            if (ch == 0) { q0 = red0[0][pp]; q1 = red0[1][pp]; q2 = red0[2][pp]; q3 = red0[3][pp]; }
            else         { q0 = red1[0][pp]; q1 = red1[1][pp]; q2 = red1[2][pp]; q3 = red1[3][pp]; }
            r = make_float4(q0.x + q1.x + q2.x + q3.x, q0.y + q1.y + q2.y + q3.y,
                            q0.z + q1.z + q2.z + q3.z, q0.w + q1.w + q2.w + q3.w);
        }
        int w0 = pp * 4;

#pragma unroll
        for (int kw = 0; kw < 5; kw++) {
            float wt = __ldg(&w_ww[(ch * S + rb) * 5 + kw]);
            atomicAdd(&s_T[kw][w0 + 0], r.x * wt);
            atomicAdd(&s_T[kw][w0 + 1], r.y * wt);
            atomicAdd(&s_T[kw][w0 + 2], r.z * wt);
            atomicAdd(&s_T[kw][w0 + 3], r.w * wt);
        }

#pragma unroll
        for (int kh = 0; kh < 5; kh++) {
            const float* whp = w_hw + (ch * 5 + kh) * S + w0;
            float pr = r.x * __ldg(whp) + r.y * __ldg(whp + 1)
                     + r.z * __ldg(whp + 2) + r.w * __ldg(whp + 3);
#pragma unroll
            for (int off = 16; off > 0; off >>= 1)
                pr += __shfl_down_sync(0xFFFFFFFFu, pr, off);
            if (pp == 0)
                atomicAdd(&g_TR[b * (10 * S) + (5 + kh) * S + rb], pr);
        }
    }
    __syncthreads();

    for (int k = tid; k < 5 * S; k += 128)
        atomicAdd(&g_TR[b * (10 * S) + k], (&s_T[0][0])[k]);
}

// ---------------------------------------------------------------------------
// K2 (PDL): halo-combine + linear + sigmoid.
// Grid = 64 = (b x branch x half), 256 threads = 8 warps x 8 outputs.
// Weight rows + biases (independent of K1) are prefetched into registers
// BEFORE cudaGridDependencySynchronize(); post-sync critical path is tiny.
// ---------------------------------------------------------------------------
__global__ void __launch_bounds__(256) k_vec(const float* __restrict__ ww_lw,
                                             const float* __restrict__ ww_lb,
                                             const float* __restrict__ hw_lw,
                                             const float* __restrict__ hw_lb) {
    int blk    = blockIdx.x;
    int b      = blk >> 2;
    int branch = (blk >> 1) & 1;       // 0 = ww, 1 = hw
    int half   = blk & 1;              // output half: j in [half*64, half*64+64)
    int tid    = threadIdx.x;
    int warp   = tid >> 5, lane = tid & 31;

    const float* lw = branch ? hw_lw : ww_lw;
    const float* lb = branch ? hw_lb : ww_lb;
    int jbase = half * 64 + warp * 8;  // this warp's 8 output rows

    // ---- prefetch (independent of K1) ----
    float4 W[8];
#pragma unroll
    for (int r = 0; r < 8; r++)
        W[r] = __ldg(reinterpret_cast<const float4*>(lw + (jbase + r) * S) + lane);
    float myb = (lane < 8) ? __ldg(&lb[jbase + lane]) : 0.f;

    // ---- wait for K1 ----
    cudaGridDependencySynchronize();

    const float* TR = g_TR + b * (10 * S) + branch * (5 * S);
    __shared__ __align__(16) float s_in[S];

    if (tid < S) {
        float acc = 0.f;
#pragma unroll
        for (int k5 = 0; k5 < 5; k5++) {
            int ip = tid + k5 - 2;
            if (ip >= 0 && ip < S) acc += TR[k5 * S + ip];
        }
        s_in[tid] = acc;
    }
    __syncthreads();

    float4 sv = reinterpret_cast<const float4*>(s_in)[lane];  // s_in[4l..4l+3]
#pragma unroll
    for (int r = 0; r < 8; r++) {
        float acc = sv.x * W[r].x + sv.y * W[r].y + sv.z * W[r].z + sv.w * W[r].w;
#pragma unroll
        for (int off = 16; off > 0; off >>= 1)
            acc += __shfl_down_sync(0xFFFFFFFFu, acc, off);
        float bias = __shfl_sync(0xFFFFFFFFu, myb, r);
        if (lane == 0) {
            acc += bias;
            g_vec[(b * 2 + branch) * S + jbase + r] = 1.f / (1.f + expf(-acc));
        }
    }
}

// ---------------------------------------------------------------------------
// K3 (PDL): outer product + re-zero g_TR for next call.
// 256 blocks x 256 threads, one float4/thread.
// ---------------------------------------------------------------------------
__global__ void __launch_bounds__(256) k_outer(float* __restrict__ out) {
    int gid = blockIdx.x * 256 + threadIdx.x;   // 0 .. 65535

    cudaGridDependencySynchronize();            // wait for k_vec

    // Re-zero TR (16*10*128 = 20480 floats); k_vec has fully consumed it.
    if (gid < BATCH * 10 * S) g_TR[gid] = 0.f;

    int b   = gid >> 12;
    int rem = gid & 4095;
    int h   = rem >> 5;
    int w4  = rem & 31;

    float hv = __ldg(&g_vec[(b * 2 + 1) * S + h]);
    float4 wv = __ldg(reinterpret_cast<const float4*>(&g_vec[(b * 2 + 0) * S]) + w4);

    reinterpret_cast<float4*>(out)[gid] =
        make_float4(hv * wv.x, hv * wv.y, hv * wv.z, hv * wv.w);
}

// ---------------------------------------------------------------------------
extern "C" void kernel_launch(void* const* d_in, const int* in_sizes, int n_in,
                              void* d_out, int out_size) {
    const float* x      = (const float*)d_in[0];
    const float* w_conv = (const float*)d_in[1];
    const float* w_ww   = (const float*)d_in[2];
    const float* w_hw   = (const float*)d_in[3];
    const float* ww_lw  = (const float*)d_in[4];
    const float* ww_lb  = (const float*)d_in[5];
    const float* hw_lw  = (const float*)d_in[6];
    const float* hw_lb  = (const float*)d_in[7];
    float* out = (float*)d_out;

    k_conv_fused<<<2048, 128>>>(x, w_conv, w_ww, w_hw);

    cudaLaunchAttribute attrs[1];
    attrs[0].id = cudaLaunchAttributeProgrammaticStreamSerialization;
    attrs[0].val.programmaticStreamSerializationAllowed = 1;

    {   // k_vec with PDL
        cudaLaunchConfig_t cfg = {};
        cfg.gridDim  = dim3(64, 1, 1);
        cfg.blockDim = dim3(256, 1, 1);
        cfg.dynamicSmemBytes = 0;
        cfg.stream = 0;
        cfg.attrs = attrs;
        cfg.numAttrs = 1;
        cudaLaunchKernelEx(&cfg, k_vec, ww_lw, ww_lb, hw_lw, hw_lb);
    }
    {   // k_outer with PDL
        cudaLaunchConfig_t cfg = {};
        cfg.gridDim  = dim3(256, 1, 1);
        cfg.blockDim = dim3(256, 1, 1);
        cfg.dynamicSmemBytes = 0;
        cfg.stream = 0;
        cfg.attrs = attrs;
        cfg.numAttrs = 1;
        cudaLaunchKernelEx(&cfg, k_outer, out);
    }
}